// round 1
// baseline (speedup 1.0000x reference)
#include <cuda_runtime.h>

#define TS   32
#define GDIM 40   // TS + 8  (gray halo 4)
#define BDIM 36   // TS + 4  (blurred halo 2)
#define MDIM 34   // TS + 2  (magnitude halo 1)
#define NTHREADS 256

__device__ __forceinline__ int reflect512(int i) {
    i = (i < 0) ? -i : i;
    return (i > 511) ? 1022 - i : i;
}
__device__ __forceinline__ int clamp511(int i) {
    return min(max(i, 0), 511);
}

__global__ __launch_bounds__(NTHREADS)
void canny_fused_kernel(const float* __restrict__ in, float* __restrict__ out)
{
    __shared__ float sg[GDIM][GDIM + 1];   // gray
    __shared__ float th[GDIM][BDIM + 1];   // horizontal blur
    __shared__ float sb[BDIM][BDIM + 1];   // full blur (edge-padded semantics via clamp)
    __shared__ float sm[MDIM][MDIM + 1];   // gradient magnitude

    const int bx0 = blockIdx.x * TS;
    const int by0 = blockIdx.y * TS;
    const int bat = blockIdx.z;
    const int tid = threadIdx.x;

    const float* base = in + (size_t)bat * 3u * 512u * 512u;

    // ---- 1) grayscale of x = (data+1)/2, tile with halo 4 (zeros outside image; never read) ----
    for (int idx = tid; idx < GDIM * GDIM; idx += NTHREADS) {
        int ly = idx / GDIM, lx = idx % GDIM;
        int ay = by0 - 4 + ly, ax = bx0 - 4 + lx;
        float g = 0.0f;
        if (ay >= 0 && ay < 512 && ax >= 0 && ax < 512) {
            int off = ay * 512 + ax;
            float r  = base[off];
            float gg = base[262144 + off];
            float bb = base[524288 + off];
            g = 0.299f * ((r  + 1.0f) * 0.5f)
              + 0.587f * ((gg + 1.0f) * 0.5f)
              + 0.114f * ((bb + 1.0f) * 0.5f);
        }
        sg[ly][lx] = g;
    }
    __syncthreads();

    // Gaussian(5, sigma=1) weights (float32, normalized)
    const float w0 = 0.054488685f;
    const float w1 = 0.24420134f;
    const float w2 = 0.40261995f;

    // ---- 2) horizontal blur with reflect padding in x ----
    // rows: all 40 local rows; cols j in [0,36) -> abs x = clamp(bx0-2+j) (edge semantics for later Sobel)
    for (int idx = tid; idx < GDIM * BDIM; idx += NTHREADS) {
        int ly = idx / BDIM, j = idx % BDIM;
        int cx = clamp511(bx0 - 2 + j);
        int o  = bx0 - 4;
        float s;
        s  = w0 * sg[ly][reflect512(cx - 2) - o];
        s += w1 * sg[ly][reflect512(cx - 1) - o];
        s += w2 * sg[ly][reflect512(cx    ) - o];
        s += w1 * sg[ly][reflect512(cx + 1) - o];
        s += w0 * sg[ly][reflect512(cx + 2) - o];
        th[ly][j] = s;
    }
    __syncthreads();

    // ---- 3) vertical blur with reflect padding in y ----
    // sb[i][j] holds blur at (clamp(by0-2+i), clamp(bx0-2+j)) == edge-padded blurred value
    for (int idx = tid; idx < BDIM * BDIM; idx += NTHREADS) {
        int i = idx / BDIM, j = idx % BDIM;
        int cy = clamp511(by0 - 2 + i);
        int o  = by0 - 4;
        float s;
        s  = w0 * th[reflect512(cy - 2) - o][j];
        s += w1 * th[reflect512(cy - 1) - o][j];
        s += w2 * th[reflect512(cy    ) - o][j];
        s += w1 * th[reflect512(cy + 1) - o][j];
        s += w0 * th[reflect512(cy + 2) - o][j];
        sb[i][j] = s;
    }
    __syncthreads();

    // ---- 4) Sobel + magnitude at tile +/- 1 halo ----
    // mag local (i,j) corresponds to abs (by0+i-1, bx0+j-1); blurred center = sb[i+1][j+1]
    for (int idx = tid; idx < MDIM * MDIM; idx += NTHREADS) {
        int i = idx / MDIM, j = idx % MDIM;
        float b00 = sb[i    ][j], b01 = sb[i    ][j + 1], b02 = sb[i    ][j + 2];
        float b10 = sb[i + 1][j],                          b12 = sb[i + 1][j + 2];
        float b20 = sb[i + 2][j], b21 = sb[i + 2][j + 1], b22 = sb[i + 2][j + 2];
        float gx = (b02 - b00) + 2.0f * (b12 - b10) + (b22 - b20);
        float gy = (b20 - b00) + 2.0f * (b21 - b01) + (b22 - b02);
        sm[i][j] = sqrtf(gx * gx + gy * gy + 1e-6f);
    }
    __syncthreads();

    // ---- 5) direction + NMS (zero padding for out-of-image neighbors) + output ----
    // offs (dy,dx): i=0..7 -> (0,1),(-1,1),(-1,0),(-1,-1),(0,-1),(1,-1),(1,0),(1,1)
    // packed nibbles: value+1 at nibble p
    const unsigned DYP = 0x22210001u;  // dy+1
    const unsigned DXP = 0x21000122u;  // dx+1

    for (int idx = tid; idx < TS * TS; idx += NTHREADS) {
        int i = idx / TS, j = idx % TS;
        int ay = by0 + i, ax = bx0 + j;
        int ii = i + 1, jj = j + 1;            // mag-local center

        // recompute Sobel at center (blurred center local (i+2, j+2))
        float b00 = sb[i + 1][j + 1], b01 = sb[i + 1][j + 2], b02 = sb[i + 1][j + 3];
        float b10 = sb[i + 2][j + 1],                          b12 = sb[i + 2][j + 3];
        float b20 = sb[i + 3][j + 1], b21 = sb[i + 3][j + 2], b22 = sb[i + 3][j + 3];
        float gx = (b02 - b00) + 2.0f * (b12 - b10) + (b22 - b20);
        float gy = (b20 - b00) + 2.0f * (b21 - b01) + (b22 - b02);

        // ang45 = round(atan2(gy,gx) * 4/pi), index = ang45 mod 8
        float t = atan2f(gy, gx) * 1.27323954473516276f;
        int ai = (int)rintf(t);
        int p = ai & 7;
        int q = (p + 4) & 7;

        int dyp = (int)((DYP >> (p * 4)) & 0xF) - 1;
        int dxp = (int)((DXP >> (p * 4)) & 0xF) - 1;
        int dyq = (int)((DYP >> (q * 4)) & 0xF) - 1;
        int dxq = (int)((DXP >> (q * 4)) & 0xF) - 1;

        float mc = sm[ii][jj];

        int nyp = ay + dyp, nxp = ax + dxp;
        float mp = (nyp >= 0 && nyp < 512 && nxp >= 0 && nxp < 512)
                 ? sm[ii + dyp][jj + dxp] : 0.0f;
        int nyq = ay + dyq, nxq = ax + dxq;
        float mq = (nyq >= 0 && nyq < 512 && nxq >= 0 && nxq < 512)
                 ? sm[ii + dyq][jj + dxq] : 0.0f;

        float selp = mc - mp;
        float selq = mc - mq;
        float r = (fminf(selp, selq) > 0.0f) ? mc : 0.0f;

        out[((size_t)bat * 512 + ay) * 512 + ax] = r;
    }
}

extern "C" void kernel_launch(void* const* d_in, const int* in_sizes, int n_in,
                              void* d_out, int out_size)
{
    (void)in_sizes; (void)n_in; (void)out_size;
    const float* data = (const float*)d_in[0];
    float* out = (float*)d_out;

    dim3 grid(512 / TS, 512 / TS, 16);
    dim3 block(NTHREADS);
    canny_fused_kernel<<<grid, block>>>(data, out);
}

// round 2
// speedup vs baseline: 1.1744x; 1.1744x over previous
#include <cuda_runtime.h>

#define TS 32

__device__ __forceinline__ int reflect512(int i) {
    i = (i < 0) ? -i : i;
    return (i > 511) ? 1022 - i : i;
}
__device__ __forceinline__ int clamp511(int i) {
    return min(max(i, 0), 511);
}

__device__ __forceinline__ float grayf(const float* __restrict__ base, int off) {
    float r  = base[off];
    float gg = base[off + 262144];
    float bb = base[off + 524288];
    // 0.299*((r+1)/2) + 0.587*((g+1)/2) + 0.114*((b+1)/2)
    return fmaf(0.1495f, r, fmaf(0.2935f, gg, fmaf(0.057f, bb, 0.5f)));
}

__global__ __launch_bounds__(256)
void canny_fused_kernel(const float* __restrict__ in, float* __restrict__ out)
{
    __shared__ float sg[40][41];            // gray (halo 4)
    __shared__ float th[40][37];            // horiz blur
    __shared__ float sb[36][37];            // full blur (edge-padded)
    __shared__ float smg[34][35];           // magnitude (halo 1)
    __shared__ unsigned char scl[34][35];   // direction class 0..3

    const int tx = threadIdx.x, ty = threadIdx.y;
    const int bx0 = blockIdx.x * TS, by0 = blockIdx.y * TS;
    const float* base = in + (size_t)blockIdx.z * 786432u;

    const float w0 = 0.054488685f, w1 = 0.24420134f, w2 = 0.40261995f;
    const bool interior = (blockIdx.x > 0u) & (blockIdx.x < 15u) &
                          (blockIdx.y > 0u) & (blockIdx.y < 15u);

    if (interior) {
        // ---- stage 1: gray 40x40, no bounds checks ----
        #pragma unroll
        for (int k = 0; k < 5; k++) {
            int ly  = ty + 8 * k;
            int off = (by0 - 4 + ly) * 512 + (bx0 - 4);
            sg[ly][tx] = grayf(base, off + tx);
            if (tx < 8) sg[ly][32 + tx] = grayf(base, off + 32 + tx);
        }
        __syncthreads();

        // ---- stage 2: horizontal blur 40x36 ----
        #pragma unroll
        for (int k = 0; k < 5; k++) {
            int ly = ty + 8 * k;
            th[ly][tx] = w0 * (sg[ly][tx] + sg[ly][tx + 4])
                       + w1 * (sg[ly][tx + 1] + sg[ly][tx + 3])
                       + w2 * sg[ly][tx + 2];
            if (tx < 4) {
                int j = tx + 32;
                th[ly][j] = w0 * (sg[ly][j] + sg[ly][j + 4])
                          + w1 * (sg[ly][j + 1] + sg[ly][j + 3])
                          + w2 * sg[ly][j + 2];
            }
        }
        __syncthreads();

        // ---- stage 3: vertical blur 36x36 ----
        #pragma unroll
        for (int k = 0; k < 5; k++) {
            int i = ty + 8 * k;
            if (i < 36) {
                sb[i][tx] = w0 * (th[i][tx] + th[i + 4][tx])
                          + w1 * (th[i + 1][tx] + th[i + 3][tx])
                          + w2 * th[i + 2][tx];
                if (tx < 4) {
                    int j = tx + 32;
                    sb[i][j] = w0 * (th[i][j] + th[i + 4][j])
                             + w1 * (th[i + 1][j] + th[i + 3][j])
                             + w2 * th[i + 2][j];
                }
            }
        }
    } else {
        // ---- stage 1 (border): gray 40x40 with zero fill ----
        #pragma unroll
        for (int k = 0; k < 5; k++) {
            int ly = ty + 8 * k;
            int ay = by0 - 4 + ly;
            bool yok = (ay >= 0) & (ay < 512);
            {
                int ax = bx0 - 4 + tx;
                float g = 0.0f;
                if (yok && ax >= 0 && ax < 512) g = grayf(base, ay * 512 + ax);
                sg[ly][tx] = g;
            }
            if (tx < 8) {
                int ax = bx0 - 4 + 32 + tx;
                float g = 0.0f;
                if (yok && ax >= 0 && ax < 512) g = grayf(base, ay * 512 + ax);
                sg[ly][32 + tx] = g;
            }
        }
        __syncthreads();

        // ---- stage 2 (border): horizontal blur with reflect-x ----
        const int ox = bx0 - 4;
        #pragma unroll
        for (int k = 0; k < 5; k++) {
            int ly = ty + 8 * k;
            {
                int cx = clamp511(bx0 - 2 + tx);
                th[ly][tx] = w0 * (sg[ly][reflect512(cx - 2) - ox] + sg[ly][reflect512(cx + 2) - ox])
                           + w1 * (sg[ly][reflect512(cx - 1) - ox] + sg[ly][reflect512(cx + 1) - ox])
                           + w2 * sg[ly][reflect512(cx) - ox];
            }
            if (tx < 4) {
                int j = tx + 32;
                int cx = clamp511(bx0 - 2 + j);
                th[ly][j] = w0 * (sg[ly][reflect512(cx - 2) - ox] + sg[ly][reflect512(cx + 2) - ox])
                          + w1 * (sg[ly][reflect512(cx - 1) - ox] + sg[ly][reflect512(cx + 1) - ox])
                          + w2 * sg[ly][reflect512(cx) - ox];
            }
        }
        __syncthreads();

        // ---- stage 3 (border): vertical blur with reflect-y ----
        const int oy = by0 - 4;
        #pragma unroll
        for (int k = 0; k < 5; k++) {
            int i = ty + 8 * k;
            if (i < 36) {
                int cy = clamp511(by0 - 2 + i);
                int r0 = reflect512(cy - 2) - oy, r1 = reflect512(cy - 1) - oy;
                int r2 = reflect512(cy) - oy;
                int r3 = reflect512(cy + 1) - oy, r4 = reflect512(cy + 2) - oy;
                sb[i][tx] = w0 * (th[r0][tx] + th[r4][tx])
                          + w1 * (th[r1][tx] + th[r3][tx])
                          + w2 * th[r2][tx];
                if (tx < 4) {
                    int j = tx + 32;
                    sb[i][j] = w0 * (th[r0][j] + th[r4][j])
                             + w1 * (th[r1][j] + th[r3][j])
                             + w2 * th[r2][j];
                }
            }
        }
    }
    __syncthreads();

    // ---- stage 4 (common): Sobel + magnitude + direction class, 34x34 ----
    #pragma unroll
    for (int k = 0; k < 5; k++) {
        int i = ty + 8 * k;
        if (i < 34) {
            #pragma unroll
            for (int h = 0; h < 2; h++) {
                int j = tx + 32 * h;
                if (h == 0 || tx < 2) {
                    float b00 = sb[i][j],     b01 = sb[i][j + 1],     b02 = sb[i][j + 2];
                    float b10 = sb[i + 1][j],                         b12 = sb[i + 1][j + 2];
                    float b20 = sb[i + 2][j], b21 = sb[i + 2][j + 1], b22 = sb[i + 2][j + 2];
                    float gx = (b02 - b00) + 2.0f * (b12 - b10) + (b22 - b20);
                    float gy = (b20 - b00) + 2.0f * (b21 - b01) + (b22 - b02);
                    smg[i][j] = sqrtf(fmaf(gx, gx, fmaf(gy, gy, 1e-6f)));
                    // octant pair: 0=horiz, 1=anti-diag(gx*gy>0), 2=vert, 3=main-diag
                    float adx = fabsf(gx), ady = fabsf(gy);
                    const float T = 0.41421356237309503f;  // tan(22.5 deg)
                    int c;
                    if (ady <= T * adx)      c = 0;
                    else if (adx <= T * ady) c = 2;
                    else c = ((__float_as_int(gx) ^ __float_as_int(gy)) >= 0) ? 1 : 3;
                    scl[i][j] = (unsigned char)c;
                }
            }
        }
    }
    __syncthreads();

    // ---- stage 5: NMS + store ----
    // per class c: first neighbor (dy1,dx1); second is the negation
    // dy1: {0,-1,-1,-1}  dx1: {1,1,0,-1}   packed as nibble(value+1)
    const unsigned DY = 0x0001u;
    const unsigned DX = 0x0122u;

    if (interior) {
        #pragma unroll
        for (int k = 0; k < 4; k++) {
            int i = ty + 8 * k, j = tx;
            int ii = i + 1, jj = j + 1;
            float mc = smg[ii][jj];
            int c  = scl[ii][jj];
            int s  = c * 4;
            int dy1 = (int)((DY >> s) & 0xFu) - 1;
            int dx1 = (int)((DX >> s) & 0xFu) - 1;
            float mp = smg[ii + dy1][jj + dx1];
            float mq = smg[ii - dy1][jj - dx1];
            float r = (mc > mp && mc > mq) ? mc : 0.0f;
            out[((size_t)blockIdx.z * 512 + (by0 + i)) * 512 + (bx0 + j)] = r;
        }
    } else {
        #pragma unroll
        for (int k = 0; k < 4; k++) {
            int i = ty + 8 * k, j = tx;
            int ii = i + 1, jj = j + 1;
            int ay = by0 + i, ax = bx0 + j;
            float mc = smg[ii][jj];
            int c  = scl[ii][jj];
            int s  = c * 4;
            int dy1 = (int)((DY >> s) & 0xFu) - 1;
            int dx1 = (int)((DX >> s) & 0xFu) - 1;
            int pyp = ay + dy1, pxp = ax + dx1;
            int pyq = ay - dy1, pxq = ax - dx1;
            float mp = (pyp >= 0 && pyp < 512 && pxp >= 0 && pxp < 512)
                     ? smg[ii + dy1][jj + dx1] : 0.0f;
            float mq = (pyq >= 0 && pyq < 512 && pxq >= 0 && pxq < 512)
                     ? smg[ii - dy1][jj - dx1] : 0.0f;
            float r = (mc > mp && mc > mq) ? mc : 0.0f;
            out[((size_t)blockIdx.z * 512 + ay) * 512 + ax] = r;
        }
    }
}

extern "C" void kernel_launch(void* const* d_in, const int* in_sizes, int n_in,
                              void* d_out, int out_size)
{
    (void)in_sizes; (void)n_in; (void)out_size;
    const float* data = (const float*)d_in[0];
    float* out = (float*)d_out;

    dim3 grid(512 / TS, 512 / TS, 16);
    dim3 block(32, 8);
    canny_fused_kernel<<<grid, block>>>(data, out);
}

// round 4
// speedup vs baseline: 1.3799x; 1.1750x over previous
#include <cuda_runtime.h>

#define NT 256

__device__ __forceinline__ int reflect512(int i) {
    i = (i < 0) ? -i : i;
    return (i > 511) ? 1022 - i : i;
}
__device__ __forceinline__ int clamp511(int i) {
    return min(max(i, 0), 511);
}
__device__ __forceinline__ float grayf(const float* __restrict__ base, int off) {
    float r = base[off], g = base[off + 262144], b = base[off + 524288];
    return fmaf(0.1495f, r, fmaf(0.2935f, g, fmaf(0.057f, b, 0.5f)));
}

__global__ __launch_bounds__(NT)
void canny_fused_kernel(const float* __restrict__ in, float* __restrict__ out)
{
    // 64x32 output tile per CTA
    __shared__ __align__(16) float sg[40][74];   // gray, halo 4 (72 cols used)
    __shared__ __align__(16) float th[40][70];   // horiz blur (68 cols used)
    __shared__ __align__(16) float smg[34][70];  // magnitude (cols 1..66 valid)
    __shared__ __align__(16) unsigned char scl[34][68];
    // vertical blur aliases dead gray buffer (36*70 <= 40*74)
    float (*sb)[70] = reinterpret_cast<float(*)[70]>(&sg[0][0]);

    const int tx = threadIdx.x, ty = threadIdx.y;
    const int bx0 = blockIdx.x * 64, by0 = blockIdx.y * 32;
    const float* base = in + (size_t)blockIdx.z * 786432u;
    const float w0 = 0.054488685f, w1 = 0.24420134f, w2 = 0.40261995f;

    const bool reflX = (blockIdx.x == 0u) | (blockIdx.x == 7u);
    const bool reflY = (blockIdx.y == 0u) | (blockIdx.y == 15u);

    // ---- stage 1: gray 40x72, abs x = bx0-4+lx ----
    if (!(reflX | reflY)) {
        #pragma unroll
        for (int k = 0; k < 5; k++) {
            int ly = ty + 8 * k;
            int off = (by0 - 4 + ly) * 512 + (bx0 - 4);
            sg[ly][tx]      = grayf(base, off + tx);
            sg[ly][tx + 32] = grayf(base, off + tx + 32);
            if (tx < 8) sg[ly][tx + 64] = grayf(base, off + tx + 64);
        }
    } else {
        #pragma unroll
        for (int k = 0; k < 5; k++) {
            int ly = ty + 8 * k;
            int ay = by0 - 4 + ly;
            bool yok = (ay >= 0) & (ay < 512);
            #pragma unroll
            for (int h = 0; h < 3; h++) {
                int lx = tx + 32 * h;
                if (h < 2 || tx < 8) {
                    int ax = bx0 - 4 + lx;
                    float g = 0.0f;
                    if (yok && ax >= 0 && ax < 512) g = grayf(base, ay * 512 + ax);
                    sg[ly][lx] = g;
                }
            }
        }
    }
    __syncthreads();

    // ---- stage 2: horizontal blur -> th cols 0..67, abs x = clamp(bx0-2+j) ----
    if (!reflX) {
        #pragma unroll
        for (int k = 0; k < 5; k++) {
            int ly = ty + 8 * k;
            #pragma unroll
            for (int h = 0; h < 2; h++) {
                int p = tx + 32 * h;
                if (h == 0 || tx < 2) {
                    float2 v0 = *(const float2*)&sg[ly][2 * p];
                    float2 v1 = *(const float2*)&sg[ly][2 * p + 2];
                    float2 v2 = *(const float2*)&sg[ly][2 * p + 4];
                    float2 o;
                    o.x = w0 * (v0.x + v2.x) + w1 * (v0.y + v1.y) + w2 * v1.x;
                    o.y = w0 * (v0.y + v2.y) + w1 * (v1.x + v2.x) + w2 * v1.y;
                    *(float2*)&th[ly][2 * p] = o;
                }
            }
        }
    } else {
        const int ox = bx0 - 4;
        #pragma unroll
        for (int k = 0; k < 5; k++) {
            int ly = ty + 8 * k;
            #pragma unroll
            for (int h = 0; h < 3; h++) {
                int j = tx + 32 * h;
                if (h < 2 || tx < 4) {
                    int cx = clamp511(bx0 - 2 + j);
                    th[ly][j] = w0 * (sg[ly][reflect512(cx - 2) - ox] + sg[ly][reflect512(cx + 2) - ox])
                              + w1 * (sg[ly][reflect512(cx - 1) - ox] + sg[ly][reflect512(cx + 1) - ox])
                              + w2 * sg[ly][reflect512(cx) - ox];
                }
            }
        }
    }
    __syncthreads();

    // ---- stage 3: vertical blur -> sb rows 0..35, abs y = clamp(by0-2+i) ----
    #pragma unroll
    for (int k = 0; k < 5; k++) {
        int i = ty + 8 * k;
        if (i < 36) {
            int r0, r1, r2, r3, r4;
            if (!reflY) { r0 = i; r1 = i + 1; r2 = i + 2; r3 = i + 3; r4 = i + 4; }
            else {
                int cy = clamp511(by0 - 2 + i), oy = by0 - 4;
                r0 = reflect512(cy - 2) - oy; r1 = reflect512(cy - 1) - oy;
                r2 = reflect512(cy) - oy;
                r3 = reflect512(cy + 1) - oy; r4 = reflect512(cy + 2) - oy;
            }
            #pragma unroll
            for (int h = 0; h < 2; h++) {
                int p = tx + 32 * h;
                if (h == 0 || tx < 2) {
                    float2 a = *(const float2*)&th[r0][2 * p];
                    float2 b = *(const float2*)&th[r1][2 * p];
                    float2 c = *(const float2*)&th[r2][2 * p];
                    float2 d = *(const float2*)&th[r3][2 * p];
                    float2 e = *(const float2*)&th[r4][2 * p];
                    float2 o;
                    o.x = w0 * (a.x + e.x) + w1 * (b.x + d.x) + w2 * c.x;
                    o.y = w0 * (a.y + e.y) + w1 * (b.y + d.y) + w2 * c.y;
                    *(float2*)&sb[i][2 * p] = o;
                }
            }
        }
    }
    __syncthreads();

    // ---- stage 4: Sobel + magnitude + class; smg[i][j], center = sb[i+1][j], j valid 1..66 ----
    #pragma unroll
    for (int k = 0; k < 5; k++) {
        int i = ty + 8 * k;
        if (i < 34) {
            #pragma unroll
            for (int h = 0; h < 2; h++) {
                int p = tx + 32 * h;
                if (h == 0 || tx < 2) {
                    int qm = max(p - 1, 0), qp = min(p + 1, 33);
                    float2 a0 = *(const float2*)&sb[i    ][2 * qm];
                    float2 b0 = *(const float2*)&sb[i    ][2 * p ];
                    float2 c0 = *(const float2*)&sb[i    ][2 * qp];
                    float2 a1 = *(const float2*)&sb[i + 1][2 * qm];
                    float2 b1 = *(const float2*)&sb[i + 1][2 * p ];
                    float2 c1 = *(const float2*)&sb[i + 1][2 * qp];
                    float2 a2 = *(const float2*)&sb[i + 2][2 * qm];
                    float2 b2 = *(const float2*)&sb[i + 2][2 * p ];
                    float2 c2 = *(const float2*)&sb[i + 2][2 * qp];

                    // col j = 2p : neighbors (a?.y | b?.x | b?.y)
                    float gx0 = (b0.y - a0.y) + 2.0f * (b1.y - a1.y) + (b2.y - a2.y);
                    float gy0 = (a2.y - a0.y) + 2.0f * (b2.x - b0.x) + (b2.y - b0.y);
                    // col j = 2p+1 : neighbors (b?.x | b?.y | c?.x)
                    float gx1 = (c0.x - b0.x) + 2.0f * (c1.x - b1.x) + (c2.x - b2.x);
                    float gy1 = (b2.x - b0.x) + 2.0f * (b2.y - b0.y) + (c2.x - c0.x);

                    float2 m;
                    m.x = sqrtf(fmaf(gx0, gx0, fmaf(gy0, gy0, 1e-6f)));
                    m.y = sqrtf(fmaf(gx1, gx1, fmaf(gy1, gy1, 1e-6f)));
                    *(float2*)&smg[i][2 * p] = m;

                    const float T = 0.41421356237309503f;  // tan(22.5 deg)
                    float ax0 = fabsf(gx0), ay0 = fabsf(gy0);
                    int c0i;
                    if (ay0 <= T * ax0)      c0i = 0;
                    else if (ax0 <= T * ay0) c0i = 2;
                    else c0i = ((__float_as_int(gx0) ^ __float_as_int(gy0)) >= 0) ? 1 : 3;
                    float ax1 = fabsf(gx1), ay1 = fabsf(gy1);
                    int c1i;
                    if (ay1 <= T * ax1)      c1i = 0;
                    else if (ax1 <= T * ay1) c1i = 2;
                    else c1i = ((__float_as_int(gx1) ^ __float_as_int(gy1)) >= 0) ? 1 : 3;
                    uchar2 cc; cc.x = (unsigned char)c0i; cc.y = (unsigned char)c1i;
                    *(uchar2*)&scl[i][2 * p] = cc;
                }
            }
        }
    }
    __syncthreads();

    // ---- stage 5: NMS + store (2 px/thread/iter) ----
    // class c -> first neighbor (dy1,dx1): c0:(0,1) c1:(-1,1) c2:(-1,0) c3:(-1,-1)
    const unsigned DY = 0x0001u, DX = 0x0122u;

    #pragma unroll
    for (int k = 0; k < 4; k++) {
        int iy = ty + 8 * k;
        int ii = iy + 1;
        int jj = 2 * tx + 2;                 // smg col of px0
        float2 mc = *(const float2*)&smg[ii][jj];
        uchar2 cc = *(const uchar2*)&scl[ii][jj];

        int s0 = cc.x * 4;
        int dy0 = (int)((DY >> s0) & 0xFu) - 1;
        int dx0 = (int)((DX >> s0) & 0xFu) - 1;
        float mp0 = smg[ii + dy0][jj + dx0];
        float mq0 = smg[ii - dy0][jj - dx0];

        int s1 = cc.y * 4;
        int dy1 = (int)((DY >> s1) & 0xFu) - 1;
        int dx1 = (int)((DX >> s1) & 0xFu) - 1;
        float mp1 = smg[ii + dy1][jj + 1 + dx1];
        float mq1 = smg[ii - dy1][jj + 1 - dx1];

        if (reflX | reflY) {
            int ay = by0 + iy;
            int ax = bx0 + 2 * tx;
            if (!((unsigned)(ay + dy0) < 512u && (unsigned)(ax + dx0) < 512u)) mp0 = 0.0f;
            if (!((unsigned)(ay - dy0) < 512u && (unsigned)(ax - dx0) < 512u)) mq0 = 0.0f;
            if (!((unsigned)(ay + dy1) < 512u && (unsigned)(ax + 1 + dx1) < 512u)) mp1 = 0.0f;
            if (!((unsigned)(ay - dy1) < 512u && (unsigned)(ax + 1 - dx1) < 512u)) mq1 = 0.0f;
        }

        float2 r;
        r.x = (mc.x > mp0 && mc.x > mq0) ? mc.x : 0.0f;
        r.y = (mc.y > mp1 && mc.y > mq1) ? mc.y : 0.0f;
        *(float2*)&out[((size_t)blockIdx.z * 512 + (by0 + iy)) * 512 + bx0 + 2 * tx] = r;
    }
}

extern "C" void kernel_launch(void* const* d_in, const int* in_sizes, int n_in,
                              void* d_out, int out_size)
{
    (void)in_sizes; (void)n_in; (void)out_size;
    const float* data = (const float*)d_in[0];
    float* out = (float*)d_out;

    dim3 grid(8, 16, 16);
    dim3 block(32, 8);
    canny_fused_kernel<<<grid, block>>>(data, out);
}